// round 12
// baseline (speedup 1.0000x reference)
#include <cuda_runtime.h>
#include <cuda.h>
#include <cstdint>

// ---------------- problem dims ----------------
#define NROWS  32768      // B*T = 64*512
#define DIN    1536       // L*IN
#define INSZ   512
#define ESZ    1024
#define H1SZ   1024
#define H2SZ   1024
#define OSZ    512

// tcgen05/TMA are arch-specific: only in the sm_103a/sm_100a cubin pass.
#if defined(__CUDA_ARCH__) && (defined(__CUDA_ARCH_FEAT_SM103_ALL) || defined(__CUDA_ARCH_FEAT_SM100_ALL) || (defined(__CUDA_ARCH_SPECIFIC__) && (__CUDA_ARCH_SPECIFIC__ >= 1000)))
#define HAS_TCGEN05 1
#else
#define HAS_TCGEN05 0
#endif

// ---------------- scratch (device globals; allocation-free) ----------------
__device__ float g_A0[(size_t)NROWS * DIN];     // gated, tf32-rounded input
__device__ float g_actA[(size_t)NROWS * 1024];  // ping
__device__ float g_actB[(size_t)NROWS * 1024];  // pong
__device__ float g_Wef[(size_t)ESZ * DIN];      // flattened+tf32 We  [E, D]
__device__ float g_W1c[(size_t)H1SZ * ESZ];
__device__ float g_W2c[(size_t)H2SZ * H1SZ];
__device__ float g_Woc[(size_t)OSZ * H2SZ];
__device__ float g_beS[ESZ];

// ---------------- helpers ----------------
__device__ __forceinline__ float tf32_rna(float x) {
    uint32_t u;
    asm("cvt.rna.tf32.f32 %0, %1;" : "=r"(u) : "f"(x));
    return __uint_as_float(u);
}

__device__ __forceinline__ uint32_t smem_addr_u32(const void* p) {
    uint32_t a;
    asm("{ .reg .u64 t; cvta.to.shared.u64 t, %1; cvt.u32.u64 %0, t; }"
        : "=r"(a) : "l"(p));
    return a;
}

// FMA-only rational tanh (Eigen-style), ~1e-6 accuracy
__device__ __forceinline__ float tanh_fast(float x) {
    float xc = fminf(fmaxf(x, -7.99881172f), 7.99881172f);
    float x2 = xc * xc;
    float p = fmaf(x2, -2.76076847742355e-16f, 2.00018790482477e-13f);
    p = fmaf(x2, p, -8.60467152213735e-11f);
    p = fmaf(x2, p, 5.12229709037114e-08f);
    p = fmaf(x2, p, 1.48572235717979e-05f);
    p = fmaf(x2, p, 6.37261928875436e-04f);
    p = fmaf(x2, p, 4.89352455891786e-03f);
    p = xc * p;
    float q = fmaf(x2, 1.19825839466702e-06f, 1.18534705686654e-04f);
    q = fmaf(x2, q, 2.26843463243900e-03f);
    q = fmaf(x2, q, 4.89352518554385e-03f);
    return __fdividef(p, q);
}

#define CP_ASYNC16(dst, src) \
    asm volatile("cp.async.cg.shared.global [%0], [%1], 16;" :: "r"(dst), "l"(src))
#define CP_COMMIT()  asm volatile("cp.async.commit_group;" ::: "memory")
#define CP_WAIT1()   asm volatile("cp.async.wait_group 1;" ::: "memory")

// ---------------- weight prep ----------------
__global__ void prep_we(const float* __restrict__ We, float* __restrict__ Wef) {
    int idx = blockIdx.x * blockDim.x + threadIdx.x;
    if (idx >= ESZ * DIN) return;
    int e = idx / DIN;
    int d = idx - e * DIN;
    int l = d >> 9;
    int i = d & 511;
    Wef[idx] = tf32_rna(We[(size_t)l * ESZ * INSZ + (size_t)e * INSZ + i]);
}

__global__ void prep_cvt(const float* __restrict__ src, float* __restrict__ dst, int n) {
    int idx = blockIdx.x * blockDim.x + threadIdx.x;
    if (idx < n) dst[idx] = tf32_rna(src[idx]);
}

__global__ void prep_besum(const float* __restrict__ be, float* __restrict__ beS) {
    int i = blockIdx.x * blockDim.x + threadIdx.x;
    if (i < ESZ) beS[i] = be[i] + be[ESZ + i] + be[2 * ESZ + i];
}

// ---------------- gate kernel ----------------
__global__ __launch_bounds__(256) void gate_kernel(const float* __restrict__ x,
                                                   const float* __restrict__ Wg,
                                                   float* __restrict__ A0) {
    __shared__ float4 sWg[3 * 384];
    const float4* Wg4 = (const float4*)Wg;
    for (int i = threadIdx.x; i < 3 * 384; i += 256) sWg[i] = Wg4[i];
    __syncthreads();

    int warp = threadIdx.x >> 5;
    int lane = threadIdx.x & 31;
    size_t row = (size_t)blockIdx.x * 8 + warp;
    const float4* xr = (const float4*)(x + row * DIN);

    float a0 = 0.f, a1 = 0.f, a2 = 0.f;
    for (int i = lane; i < 384; i += 32) {
        float4 v = xr[i];
        float4 w0 = sWg[i], w1 = sWg[384 + i], w2 = sWg[768 + i];
        a0 += v.x * w0.x + v.y * w0.y + v.z * w0.z + v.w * w0.w;
        a1 += v.x * w1.x + v.y * w1.y + v.z * w1.z + v.w * w1.w;
        a2 += v.x * w2.x + v.y * w2.y + v.z * w2.z + v.w * w2.w;
    }
    #pragma unroll
    for (int off = 16; off; off >>= 1) {
        a0 += __shfl_xor_sync(0xffffffffu, a0, off);
        a1 += __shfl_xor_sync(0xffffffffu, a1, off);
        a2 += __shfl_xor_sync(0xffffffffu, a2, off);
    }
    float g0 = 1.f / (1.f + expf(-a0));
    float g1 = 1.f / (1.f + expf(-a1));
    float g2 = 1.f / (1.f + expf(-a2));

    float4* ar = (float4*)(A0 + row * DIN);
    for (int i = lane; i < 384; i += 32) {
        float4 v = xr[i];
        float gv = (i < 128) ? g0 : ((i < 256) ? g1 : g2);
        float4 o;
        o.x = tf32_rna(v.x * gv);
        o.y = tf32_rna(v.y * gv);
        o.z = tf32_rna(v.z * gv);
        o.w = tf32_rna(v.w * gv);
        ar[i] = o;
    }
}

#define ACT_NONE 0
#define ACT_RELU 1
#define ACT_TANH 2

// ======================================================================
// tcgen05-only helpers (emitted only in the arch-specific pass)
// ======================================================================
#if HAS_TCGEN05

__device__ __forceinline__ bool elect_one() {
    uint32_t p;
    asm volatile("{\n\t.reg .pred P;\n\telect.sync _|P, 0xFFFFFFFF;\n\tselp.b32 %0, 1, 0, P;\n\t}"
                 : "=r"(p));
    return p != 0;
}

#define MBAR_INIT(a, n) \
    asm volatile("mbarrier.init.shared.b64 [%0], %1;" :: "r"(a), "r"((uint32_t)(n)) : "memory")

#define MBAR_WAIT(a, ph) do {                                                   \
    uint32_t done_;                                                             \
    asm volatile("{\n\t.reg .pred P;\n\t"                                       \
        "mbarrier.try_wait.parity.acquire.cta.shared::cta.b64 P, [%1], %2;\n\t" \
        "selp.b32 %0, 1, 0, P;\n\t}"                                            \
        : "=r"(done_) : "r"(a), "r"((uint32_t)(ph)) : "memory");                \
    if (!done_) {                                                               \
        asm volatile("{\n\t.reg .pred P1;\n\t"                                  \
            "WL%=:\n\t"                                                         \
            "mbarrier.try_wait.parity.acquire.cta.shared::cta.b64 P1, [%0], %1, 0x989680;\n\t" \
            "@P1 bra.uni WD%=;\n\t"                                             \
            "bra.uni WL%=;\n\t"                                                 \
            "WD%=:\n\t}"                                                        \
            :: "r"(a), "r"((uint32_t)(ph)) : "memory");                         \
    }                                                                           \
} while (0)

#define MBAR_EXPECT_TX(a, bytes) \
    asm volatile("mbarrier.arrive.expect_tx.shared.b64 _, [%0], %1;" \
                 :: "r"(a), "r"((uint32_t)(bytes)) : "memory")

// cg2 TMA: data to MY smem; complete_tx to the LEADER CTA's barrier
// (bit 24 = Sm100MmaPeerBitMask cleared -> rank-0 of the pair).
#define TMA_2D_CG2(dst, map, cx, cy, mbar) \
    asm volatile("{\n\t.reg .b32 lb;\n\tand.b32 lb, %4, 0xFEFFFFFF;\n\t" \
        "cp.async.bulk.tensor.2d.cta_group::2.shared::cluster.global.tile.mbarrier::complete_tx::bytes " \
        "[%0], [%1, {%2, %3}], [lb];\n\t}" \
        :: "r"(dst), "l"(map), "r"((int)(cx)), "r"((int)(cy)), "r"(mbar) : "memory")

#define TC_ALLOC_CG2(sa, n) \
    asm volatile("tcgen05.alloc.cta_group::2.sync.aligned.shared::cta.b32 [%0], %1;" \
                 :: "r"(sa), "r"((uint32_t)(n)) : "memory")
#define TC_RELINQ_CG2() \
    asm volatile("tcgen05.relinquish_alloc_permit.cta_group::2.sync.aligned;")
#define TC_DEALLOC_CG2(t, n) \
    asm volatile("tcgen05.dealloc.cta_group::2.sync.aligned.b32 %0, %1;" \
                 :: "r"(t), "r"((uint32_t)(n)))
// cg2 commit, multicast to both pair CTAs' reuse barrier (same smem offset)
#define TC_COMMIT_MC_CG2(mb, mask) \
    asm volatile("tcgen05.commit.cta_group::2.mbarrier::arrive::one.shared::cluster.multicast::cluster.b64 [%0], %1;" \
                 :: "r"(mb), "h"((uint16_t)(mask)) : "memory")
#define TC_FENCE_AFTER() \
    asm volatile("tcgen05.fence::after_thread_sync;" ::: "memory")
#define TC_WAIT_LD() \
    asm volatile("tcgen05.wait::ld.sync.aligned;" ::: "memory")

#define CLUSTER_SYNC() do { \
    asm volatile("barrier.cluster.arrive.aligned;" ::: "memory"); \
    asm volatile("barrier.cluster.wait.aligned;" ::: "memory"); \
} while (0)

#define TC_LD_32X32B_X32(r, ta)                                                 \
    asm volatile(                                                               \
        "tcgen05.ld.sync.aligned.32x32b.x32.b32 "                               \
        "{%0, %1, %2, %3, %4, %5, %6, %7, "                                     \
        " %8, %9, %10, %11, %12, %13, %14, %15, "                               \
        " %16, %17, %18, %19, %20, %21, %22, %23, "                             \
        " %24, %25, %26, %27, %28, %29, %30, %31}, [%32];"                      \
        : "=r"((r)[0]),  "=r"((r)[1]),  "=r"((r)[2]),  "=r"((r)[3]),            \
          "=r"((r)[4]),  "=r"((r)[5]),  "=r"((r)[6]),  "=r"((r)[7]),            \
          "=r"((r)[8]),  "=r"((r)[9]),  "=r"((r)[10]), "=r"((r)[11]),           \
          "=r"((r)[12]), "=r"((r)[13]), "=r"((r)[14]), "=r"((r)[15]),           \
          "=r"((r)[16]), "=r"((r)[17]), "=r"((r)[18]), "=r"((r)[19]),           \
          "=r"((r)[20]), "=r"((r)[21]), "=r"((r)[22]), "=r"((r)[23]),           \
          "=r"((r)[24]), "=r"((r)[25]), "=r"((r)[26]), "=r"((r)[27]),           \
          "=r"((r)[28]), "=r"((r)[29]), "=r"((r)[30]), "=r"((r)[31])            \
        : "r"(ta))

// SS mma, cta_group::2, kind::tf32 (K=8 per dispatch, M=256 across the pair)
__device__ __forceinline__ void mma_tf32_cg2(uint32_t d, uint64_t ad, uint64_t bd,
                                             uint32_t idesc, uint32_t en) {
    asm volatile(
        "{\n\t.reg .pred p;\n\tsetp.ne.u32 p, %4, 0;\n\t"
        "tcgen05.mma.cta_group::2.kind::tf32 [%0], %1, %2, %3, "
        "{%5, %5, %5, %5, %5, %5, %5, %5}, p;\n\t}\n"
        :: "r"(d), "l"(ad), "l"(bd), "r"(idesc), "r"(en), "r"(0u) : "memory");
}

// SW128 K-major descriptor: layout=2, version=1, SBO=64, LBO=1
__device__ __forceinline__ uint64_t smem_desc_sw128(uint32_t addr) {
    return (2ull << 61) | (1ull << 46) | (64ull << 32) | (1ull << 16)
         | ((uint64_t)(addr >> 4) & 0x3FFF);
}

#endif  // HAS_TCGEN05

// ======================================================================
// cg2 tcgen05 tf32 GEMM: C[M,N] = act(A[M,K] @ B[N,K]^T + bias[N])
// Cluster (2,1,1): cg2 pairs MUST be adjacent along cluster X
// (CUTLASS 2sm constraint; (1,2,1) fails launch with "cluster
// misconfiguration"). Pair computes BM=256 (M=256 cg2 atom, A split
// 128/CTA) x BN=512 (two N=256 cg2 MMAs; B split 128 rows/CTA). BK=32.
// Per CTA per kt: A 16KB + B 32KB = 48KB -> 0.75 B/elem LTS traffic.
// 3-stage TMA ring; all complete_tx -> leader full barrier (96KB);
// leader MMAs + cg2 commit-multicast -> both reuse barriers gate refills.
// grid = (NROWS/128, N/512): M-tiles along X (paired), N-tiles along Y.
// ======================================================================
#define STAGE_BYTES  49152                       // A 16KB + B 32KB
#define GEMM_SMEM_BYTES (1024 + 3 * STAGE_BYTES) // 148480

template <int ACT, bool ROUND>
__global__ void __launch_bounds__(128, 1) __cluster_dims__(2, 1, 1)
gemm_tc(const __grid_constant__ CUtensorMap tmA,
        const __grid_constant__ CUtensorMap tmB,
        const float* __restrict__ bias, float* __restrict__ C,
        int N, int K) {
#if HAS_TCGEN05
    extern __shared__ char smem[];
    const uint32_t sbase = smem_addr_u32(smem);
    const int tid  = threadIdx.x;
    const int wid  = tid >> 5;
    const int lane = tid & 31;

    uint32_t rank;
    asm("mov.u32 %0, %%cluster_ctarank;" : "=r"(rank));

    // ctrl block: [0..4) tmem ptr, full[3] at +8/+16/+24 (leader-used),
    // reuse[3] at +32/+40/+48
    const uint32_t fullb0 = sbase + 8;
    const uint32_t reub0  = sbase + 32;
    const uint32_t tb = (sbase + 64 + 1023) & ~1023u;   // 1KB-aligned tile base
    const uint32_t aBase[3] = { tb, tb + STAGE_BYTES, tb + 2 * STAGE_BYTES };

    if (tid == 0) {
        #pragma unroll
        for (int s = 0; s < 3; s++) {
            MBAR_INIT(fullb0 + s * 8, 1);          // 1 arrive: leader's expect_tx
            MBAR_INIT(reub0 + s * 8, 1);           // 1 arrive: cg2 commit-mc
        }
    }
    if (wid == 0) { TC_ALLOC_CG2(sbase, 512); TC_RELINQ_CG2(); }
    __syncthreads();
    uint32_t tmem;
    asm volatile("ld.shared.b32 %0, [%1];" : "=r"(tmem) : "r"(sbase));

    // barriers + TMEM alloc visible pair-wide before any TMA/MMA
    CLUSTER_SYNC();

    const int bRowCTA = blockIdx.x * 128;          // this CTA's 128 A/D rows
    const int bCol = blockIdx.y * 512;
    const int KT = K >> 5;
    const bool leader = (rank == 0);

    if (wid == 0 && elect_one()) {
        auto issue = [&](int s, int k0) {
            const uint32_t fb = fullb0 + s * 8;
            if (leader) MBAR_EXPECT_TX(fb, 2 * 49152u);   // pair total 96KB
            // A: my 128 M-rows
            TMA_2D_CG2(aBase[s], &tmA, k0, bRowCTA, fb);
            // B halves: MMA h reads N-rows [h*256 + rank*128, +128) from my smem
            TMA_2D_CG2(aBase[s] + 16384, &tmB, k0, bCol + (int)rank * 128, fb);
            TMA_2D_CG2(aBase[s] + 32768, &tmB, k0, bCol + 256 + (int)rank * 128, fb);
        };

        // prologue: stages 0..2
        issue(0, 0);
        issue(1, 32);
        issue(2, 64);

        int ff[3] = { 0, 0, 0 };
        int rr[3] = { 0, 0, 0 };
        // idesc: dtype=F32(1<<4), atype=btype=TF32(2), N=256, M=256 (cg2)
        const uint32_t IDESC = (1u << 4) | (2u << 7) | (2u << 10)
                             | ((256u / 8) << 17) | ((256u / 16) << 24);

        for (int kt = 0; kt < KT; kt++) {
            const int s = kt - (kt / 3) * 3;       // kt % 3
            if (leader) {
                MBAR_WAIT(fullb0 + s * 8, ff[s]); ff[s] ^= 1;
                uint64_t aD = smem_desc_sw128(aBase[s]);
                #pragma unroll
                for (int h = 0; h < 2; h++) {
                    uint64_t bD = smem_desc_sw128(aBase[s] + 16384 + h * 16384);
                    #pragma unroll
                    for (int ks = 0; ks < 4; ks++)
                        mma_tf32_cg2(tmem + h * 256,
                                     aD + ks * 2,
                                     bD + ks * 2,
                                     IDESC,
                                     (kt > 0 || ks > 0) ? 1u : 0u);
                }
                TC_COMMIT_MC_CG2(reub0 + s * 8, 0x3);
            }

            if (kt + 3 < KT) {
                // pair-wide MMAs of round kt must retire before stage s refill
                MBAR_WAIT(reub0 + s * 8, rr[s]); rr[s] ^= 1;
                issue(s, (kt + 3) * 32);
            }
        }

        // final: wait the last commit (commits complete in order)
        const int sl = (KT - 1) - ((KT - 1) / 3) * 3;
        MBAR_WAIT(reub0 + sl * 8, rr[sl]);
    }
    TC_FENCE_AFTER();
    __syncthreads();

    // ---- epilogue: my TMEM 128 rows x 512 cols -> bias/act/round -> smem
    // transpose -> coalesced STG. 16 chunks of 32 cols.
    float* ep = (float*)(smem + (tb - sbase));    // 2 x [128][33] staging
    for (int ch = 0; ch < 16; ch++) {
        uint32_t dreg[32];
        TC_LD_32X32B_X32(dreg, tmem + ch * 32);
        TC_WAIT_LD();
        float* buf = ep + (ch & 1) * (128 * 33);
        #pragma unroll
        for (int j = 0; j < 32; j++) {
            float v = __uint_as_float(dreg[j]) + bias[bCol + ch * 32 + j];
            if (ACT == ACT_RELU) v = fmaxf(v, 0.f);
            if (ACT == ACT_TANH) v = tanh_fast(v);
            if (ROUND) v = tf32_rna(v);
            buf[tid * 33 + j] = v;
        }
        __syncthreads();
        #pragma unroll
        for (int jj = 0; jj < 32; jj++) {
            int r = wid + jj * 4;
            C[(size_t)(bRowCTA + r) * N + bCol + ch * 32 + lane] = buf[r * 33 + lane];
        }
        __syncthreads();
    }
    if (wid == 0) TC_DEALLOC_CG2(tmem, 512);
    // no CTA exits while peer traffic (TMA complete_tx / commit-mc / peer
    // smem reads by MMA) may still target it
    CLUSTER_SYNC();
#else
    (void)bias; (void)C; (void)N; (void)K;
#endif
}

// ======================================================================
// Fallback mma.sync tf32 GEMM (round-4 proven kernel).
// No-op body in the arch-specific pass (tcgen05 kernel runs instead).
// ======================================================================
template <int ACT, bool ROUND>
__global__ __launch_bounds__(256) void gemm_fb(const float* __restrict__ A,
                                               const float* __restrict__ B,
                                               const float* __restrict__ bias,
                                               float* __restrict__ C,
                                               int M, int N, int K) {
#if !HAS_TCGEN05
    __shared__ float As[2][128][20];
    __shared__ float Bs[2][128][20];

    const int tid  = threadIdx.x;
    const int bRow = blockIdx.y * 128;
    const int bCol = blockIdx.x * 128;
    const int warp = tid >> 5;
    const int lane = tid & 31;
    const int wRow = (warp >> 2) * 64;
    const int wCol = (warp & 3) * 32;
    const int g = lane >> 2;
    const int t = lane & 3;

    float acc[4][4][4];
    #pragma unroll
    for (int i = 0; i < 4; i++)
        #pragma unroll
        for (int j = 0; j < 4; j++)
            #pragma unroll
            for (int r = 0; r < 4; r++) acc[i][j][r] = 0.f;

    auto load_stage = [&](int s, int kt) {
        int k0 = kt * 16;
        #pragma unroll
        for (int it = 0; it < 2; it++) {
            int idx = tid + it * 256;
            int r = idx >> 2;
            int c = (idx & 3) << 2;
            const float* ga = A + (size_t)(bRow + r) * K + k0 + c;
            unsigned da = (unsigned)__cvta_generic_to_shared(&As[s][r][c]);
            CP_ASYNC16(da, ga);
            const float* gb = B + (size_t)(bCol + r) * K + k0 + c;
            unsigned db = (unsigned)__cvta_generic_to_shared(&Bs[s][r][c]);
            CP_ASYNC16(db, gb);
        }
    };

    const int KT = K >> 4;
    load_stage(0, 0); CP_COMMIT();
    load_stage(1, 1); CP_COMMIT();
    CP_WAIT1();
    __syncthreads();

    for (int kt = 0; kt < KT; kt++) {
        int s = kt & 1;
        #pragma unroll
        for (int ks = 0; ks < 2; ks++) {
            int k0 = ks * 8;
            unsigned af[4][4];
            unsigned bf[4][2];
            #pragma unroll
            for (int mt = 0; mt < 4; mt++) {
                int r = wRow + mt * 16 + g;
                af[mt][0] = __float_as_uint(As[s][r][k0 + t]);
                af[mt][1] = __float_as_uint(As[s][r + 8][k0 + t]);
                af[mt][2] = __float_as_uint(As[s][r][k0 + t + 4]);
                af[mt][3] = __float_as_uint(As[s][r + 8][k0 + t + 4]);
            }
            #pragma unroll
            for (int nt = 0; nt < 4; nt++) {
                int c = wCol + nt * 8 + g;
                bf[nt][0] = __float_as_uint(Bs[s][c][k0 + t]);
                bf[nt][1] = __float_as_uint(Bs[s][c][k0 + t + 4]);
            }
            #pragma unroll
            for (int mt = 0; mt < 4; mt++)
                #pragma unroll
                for (int nt = 0; nt < 4; nt++) {
                    asm volatile(
                        "mma.sync.aligned.m16n8k8.row.col.f32.tf32.tf32.f32 "
                        "{%0,%1,%2,%3}, {%4,%5,%6,%7}, {%8,%9}, {%0,%1,%2,%3};"
                        : "+f"(acc[mt][nt][0]), "+f"(acc[mt][nt][1]),
                          "+f"(acc[mt][nt][2]), "+f"(acc[mt][nt][3])
                        : "r"(af[mt][0]), "r"(af[mt][1]), "r"(af[mt][2]), "r"(af[mt][3]),
                          "r"(bf[nt][0]), "r"(bf[nt][1]));
                }
        }
        __syncthreads();
        if (kt + 2 < KT) load_stage(s, kt + 2);
        CP_COMMIT();
        CP_WAIT1();
        __syncthreads();
    }

    #pragma unroll
    for (int mt = 0; mt < 4; mt++) {
        int r0 = bRow + wRow + mt * 16 + g;
        #pragma unroll
        for (int nt = 0; nt < 4; nt++) {
            int c0 = bCol + wCol + nt * 8 + t * 2;
            float bv0 = bias[c0], bv1 = bias[c0 + 1];
            float v0 = acc[mt][nt][0] + bv0;
            float v1 = acc[mt][nt][1] + bv1;
            float v2 = acc[mt][nt][2] + bv0;
            float v3 = acc[mt][nt][3] + bv1;
            if (ACT == ACT_RELU) {
                v0 = fmaxf(v0, 0.f); v1 = fmaxf(v1, 0.f);
                v2 = fmaxf(v2, 0.f); v3 = fmaxf(v3, 0.f);
            } else if (ACT == ACT_TANH) {
                v0 = tanh_fast(v0); v1 = tanh_fast(v1);
                v2 = tanh_fast(v2); v3 = tanh_fast(v3);
            }
            if (ROUND) {
                v0 = tf32_rna(v0); v1 = tf32_rna(v1);
                v2 = tf32_rna(v2); v3 = tf32_rna(v3);
            }
            float2 p0; p0.x = v0; p0.y = v1;
            float2 p1; p1.x = v2; p1.y = v3;
            *(float2*)(C + (size_t)r0 * N + c0)       = p0;
            *(float2*)(C + (size_t)(r0 + 8) * N + c0) = p1;
        }
    }
#else
    (void)A; (void)B; (void)bias; (void)C; (void)M; (void)N; (void)K;
#endif
}

// ---------------- host-side tensormap builder ----------------
typedef CUresult (*cuTensorMapEncodeTiled_t)(
    CUtensorMap*, CUtensorMapDataType, cuuint32_t, void*,
    const cuuint64_t*, const cuuint64_t*, const cuuint32_t*, const cuuint32_t*,
    CUtensorMapInterleave, CUtensorMapSwizzle, CUtensorMapL2promotion,
    CUtensorMapFloatOOBfill);

static cuTensorMapEncodeTiled_t get_enc() {
    static cuTensorMapEncodeTiled_t fn = nullptr;
    if (!fn) {
        cudaDriverEntryPointQueryResult st;
#if CUDART_VERSION >= 12050
        cudaGetDriverEntryPointByVersion("cuTensorMapEncodeTiled", (void**)&fn,
                                         12000, cudaEnableDefault, &st);
#else
        cudaGetDriverEntryPoint("cuTensorMapEncodeTiled", (void**)&fn,
                                cudaEnableDefault, &st);
#endif
    }
    return fn;
}

// 2D map over row-major [rows, K] float matrix; box (32 cols, 128 rows), SW128
static void make_map(CUtensorMap* m, float* base, int K, int rows) {
    cuuint64_t dims[2]    = { (cuuint64_t)K, (cuuint64_t)rows };
    cuuint64_t strides[1] = { (cuuint64_t)K * 4 };
    cuuint32_t box[2]     = { 32u, 128u };
    cuuint32_t es[2]      = { 1u, 1u };
    cuTensorMapEncodeTiled_t enc = get_enc();
    if (enc)
        enc(m, CU_TENSOR_MAP_DATA_TYPE_FLOAT32, 2, base, dims, strides, box, es,
            CU_TENSOR_MAP_INTERLEAVE_NONE, CU_TENSOR_MAP_SWIZZLE_128B,
            CU_TENSOR_MAP_L2_PROMOTION_L2_128B, CU_TENSOR_MAP_FLOAT_OOB_FILL_NONE);
}

// ---------------- launch ----------------
extern "C" void kernel_launch(void* const* d_in, const int* in_sizes, int n_in,
                              void* d_out, int out_size) {
    (void)in_sizes; (void)n_in; (void)out_size;
    const float* x  = (const float*)d_in[0];
    const float* Wg = (const float*)d_in[1];
    const float* We = (const float*)d_in[2];
    const float* be = (const float*)d_in[3];
    const float* W1 = (const float*)d_in[4];
    const float* b1 = (const float*)d_in[5];
    const float* W2 = (const float*)d_in[6];
    const float* b2 = (const float*)d_in[7];
    const float* Wo = (const float*)d_in[8];
    const float* bo = (const float*)d_in[9];
    float* out = (float*)d_out;

    float *A0, *actA, *actB, *Wef, *W1c, *W2c, *Woc, *beS;
    cudaGetSymbolAddress((void**)&A0,  g_A0);
    cudaGetSymbolAddress((void**)&actA, g_actA);
    cudaGetSymbolAddress((void**)&actB, g_actB);
    cudaGetSymbolAddress((void**)&Wef, g_Wef);
    cudaGetSymbolAddress((void**)&W1c, g_W1c);
    cudaGetSymbolAddress((void**)&W2c, g_W2c);
    cudaGetSymbolAddress((void**)&Woc, g_Woc);
    cudaGetSymbolAddress((void**)&beS, g_beS);

    // tensormaps (host-built, passed by value; snapshot at graph capture)
    CUtensorMap mA0{}, mAA{}, mAB{}, mWe{}, mW1{}, mW2{}, mWo{};
    make_map(&mA0, A0,  DIN,  NROWS);
    make_map(&mAA, actA, 1024, NROWS);
    make_map(&mAB, actB, 1024, NROWS);
    make_map(&mWe, Wef, DIN,  ESZ);
    make_map(&mW1, W1c, ESZ,  H1SZ);
    make_map(&mW2, W2c, H1SZ, H2SZ);
    make_map(&mWo, Woc, H2SZ, OSZ);

    cudaFuncSetAttribute(gemm_tc<ACT_RELU, true>,
                         cudaFuncAttributeMaxDynamicSharedMemorySize, GEMM_SMEM_BYTES);
    cudaFuncSetAttribute(gemm_tc<ACT_TANH, true>,
                         cudaFuncAttributeMaxDynamicSharedMemorySize, GEMM_SMEM_BYTES);
    cudaFuncSetAttribute(gemm_tc<ACT_NONE, false>,
                         cudaFuncAttributeMaxDynamicSharedMemorySize, GEMM_SMEM_BYTES);

    // weight prep (cheap, idempotent)
    prep_we<<<(ESZ * DIN + 255) / 256, 256>>>(We, Wef);
    prep_cvt<<<(H1SZ * ESZ + 255) / 256, 256>>>(W1, W1c, H1SZ * ESZ);
    prep_cvt<<<(H2SZ * H1SZ + 255) / 256, 256>>>(W2, W2c, H2SZ * H1SZ);
    prep_cvt<<<(OSZ * H2SZ + 255) / 256, 256>>>(Wo, Woc, OSZ * H2SZ);
    prep_besum<<<(ESZ + 255) / 256, 256>>>(be, beS);

    // gates + gated/rounded A0
    gate_kernel<<<NROWS / 8, 256>>>(x, Wg, A0);

    // Fallback chain (no-op bodies when the sm_103a-specific cubin is loaded)
    gemm_fb<ACT_RELU, true><<<dim3(ESZ / 128, NROWS / 128), 256>>>(A0, Wef, beS, actA, NROWS, ESZ, DIN);
    gemm_fb<ACT_TANH, true><<<dim3(H1SZ / 128, NROWS / 128), 256>>>(actA, W1c, b1, actB, NROWS, H1SZ, ESZ);
    gemm_fb<ACT_TANH, true><<<dim3(H2SZ / 128, NROWS / 128), 256>>>(actB, W2c, b2, actA, NROWS, H2SZ, H1SZ);
    gemm_fb<ACT_NONE, false><<<dim3(OSZ / 128, NROWS / 128), 256>>>(actA, Woc, bo, out, NROWS, OSZ, H2SZ);

    // cg2 tcgen05 chain (no-op bodies in the generic pass):
    // cluster (2,1,1): M-tiles along X (paired), N-tiles along Y.
    // grid = (NROWS/128, N/512); pair tile = 256x512.
    gemm_tc<ACT_RELU, true><<<dim3(NROWS / 128, ESZ / 512), 128, GEMM_SMEM_BYTES>>>(
        mA0, mWe, beS, actA, ESZ, DIN);
    gemm_tc<ACT_TANH, true><<<dim3(NROWS / 128, H1SZ / 512), 128, GEMM_SMEM_BYTES>>>(
        mAA, mW1, b1, actB, H1SZ, ESZ);
    gemm_tc<ACT_TANH, true><<<dim3(NROWS / 128, H2SZ / 512), 128, GEMM_SMEM_BYTES>>>(
        mAB, mW2, b2, actA, H2SZ, H1SZ);
    gemm_tc<ACT_NONE, false><<<dim3(NROWS / 128, OSZ / 512), 128, GEMM_SMEM_BYTES>>>(
        mAA, mWo, bo, out, OSZ, H2SZ);
}

// round 14
// speedup vs baseline: 1.0083x; 1.0083x over previous
#include <cuda_runtime.h>
#include <cuda.h>
#include <cstdint>

// ---------------- problem dims ----------------
#define NROWS  32768      // B*T = 64*512
#define DIN    1536       // L*IN
#define INSZ   512
#define ESZ    1024
#define H1SZ   1024
#define H2SZ   1024
#define OSZ    512

// tcgen05/TMA are arch-specific: only in the sm_103a/sm_100a cubin pass.
#if defined(__CUDA_ARCH__) && (defined(__CUDA_ARCH_FEAT_SM103_ALL) || defined(__CUDA_ARCH_FEAT_SM100_ALL) || (defined(__CUDA_ARCH_SPECIFIC__) && (__CUDA_ARCH_SPECIFIC__ >= 1000)))
#define HAS_TCGEN05 1
#else
#define HAS_TCGEN05 0
#endif

// ---------------- scratch (device globals; allocation-free) ----------------
__device__ float g_A0[(size_t)NROWS * DIN];     // gated, tf32-rounded input
__device__ float g_actA[(size_t)NROWS * 1024];  // ping
__device__ float g_actB[(size_t)NROWS * 1024];  // pong
__device__ float g_Wef[(size_t)ESZ * DIN];      // flattened+tf32 We  [E, D]
__device__ float g_W1c[(size_t)H1SZ * ESZ];
__device__ float g_W2c[(size_t)H2SZ * H1SZ];
__device__ float g_Woc[(size_t)OSZ * H2SZ];
__device__ float g_beS[ESZ];

// ---------------- helpers ----------------
__device__ __forceinline__ float tf32_rna(float x) {
    uint32_t u;
    asm("cvt.rna.tf32.f32 %0, %1;" : "=r"(u) : "f"(x));
    return __uint_as_float(u);
}

__device__ __forceinline__ uint32_t smem_addr_u32(const void* p) {
    uint32_t a;
    asm("{ .reg .u64 t; cvta.to.shared.u64 t, %1; cvt.u32.u64 %0, t; }"
        : "=r"(a) : "l"(p));
    return a;
}

// FMA-only rational tanh (Eigen-style), ~1e-6 accuracy
__device__ __forceinline__ float tanh_fast(float x) {
    float xc = fminf(fmaxf(x, -7.99881172f), 7.99881172f);
    float x2 = xc * xc;
    float p = fmaf(x2, -2.76076847742355e-16f, 2.00018790482477e-13f);
    p = fmaf(x2, p, -8.60467152213735e-11f);
    p = fmaf(x2, p, 5.12229709037114e-08f);
    p = fmaf(x2, p, 1.48572235717979e-05f);
    p = fmaf(x2, p, 6.37261928875436e-04f);
    p = fmaf(x2, p, 4.89352455891786e-03f);
    p = xc * p;
    float q = fmaf(x2, 1.19825839466702e-06f, 1.18534705686654e-04f);
    q = fmaf(x2, q, 2.26843463243900e-03f);
    q = fmaf(x2, q, 4.89352518554385e-03f);
    return __fdividef(p, q);
}

#define CP_ASYNC16(dst, src) \
    asm volatile("cp.async.cg.shared.global [%0], [%1], 16;" :: "r"(dst), "l"(src))
#define CP_COMMIT()  asm volatile("cp.async.commit_group;" ::: "memory")
#define CP_WAIT1()   asm volatile("cp.async.wait_group 1;" ::: "memory")

// ---------------- weight prep ----------------
__global__ void prep_we(const float* __restrict__ We, float* __restrict__ Wef) {
    int idx = blockIdx.x * blockDim.x + threadIdx.x;
    if (idx >= ESZ * DIN) return;
    int e = idx / DIN;
    int d = idx - e * DIN;
    int l = d >> 9;
    int i = d & 511;
    Wef[idx] = tf32_rna(We[(size_t)l * ESZ * INSZ + (size_t)e * INSZ + i]);
}

__global__ void prep_cvt(const float* __restrict__ src, float* __restrict__ dst, int n) {
    int idx = blockIdx.x * blockDim.x + threadIdx.x;
    if (idx < n) dst[idx] = tf32_rna(src[idx]);
}

__global__ void prep_besum(const float* __restrict__ be, float* __restrict__ beS) {
    int i = blockIdx.x * blockDim.x + threadIdx.x;
    if (i < ESZ) beS[i] = be[i] + be[ESZ + i] + be[2 * ESZ + i];
}

// ---------------- gate kernel ----------------
__global__ __launch_bounds__(256) void gate_kernel(const float* __restrict__ x,
                                                   const float* __restrict__ Wg,
                                                   float* __restrict__ A0) {
    __shared__ float4 sWg[3 * 384];
    const float4* Wg4 = (const float4*)Wg;
    for (int i = threadIdx.x; i < 3 * 384; i += 256) sWg[i] = Wg4[i];
    __syncthreads();

    int warp = threadIdx.x >> 5;
    int lane = threadIdx.x & 31;
    size_t row = (size_t)blockIdx.x * 8 + warp;
    const float4* xr = (const float4*)(x + row * DIN);

    float a0 = 0.f, a1 = 0.f, a2 = 0.f;
    for (int i = lane; i < 384; i += 32) {
        float4 v = xr[i];
        float4 w0 = sWg[i], w1 = sWg[384 + i], w2 = sWg[768 + i];
        a0 += v.x * w0.x + v.y * w0.y + v.z * w0.z + v.w * w0.w;
        a1 += v.x * w1.x + v.y * w1.y + v.z * w1.z + v.w * w1.w;
        a2 += v.x * w2.x + v.y * w2.y + v.z * w2.z + v.w * w2.w;
    }
    #pragma unroll
    for (int off = 16; off; off >>= 1) {
        a0 += __shfl_xor_sync(0xffffffffu, a0, off);
        a1 += __shfl_xor_sync(0xffffffffu, a1, off);
        a2 += __shfl_xor_sync(0xffffffffu, a2, off);
    }
    float g0 = 1.f / (1.f + expf(-a0));
    float g1 = 1.f / (1.f + expf(-a1));
    float g2 = 1.f / (1.f + expf(-a2));

    float4* ar = (float4*)(A0 + row * DIN);
    for (int i = lane; i < 384; i += 32) {
        float4 v = xr[i];
        float gv = (i < 128) ? g0 : ((i < 256) ? g1 : g2);
        float4 o;
        o.x = tf32_rna(v.x * gv);
        o.y = tf32_rna(v.y * gv);
        o.z = tf32_rna(v.z * gv);
        o.w = tf32_rna(v.w * gv);
        ar[i] = o;
    }
}

#define ACT_NONE 0
#define ACT_RELU 1
#define ACT_TANH 2

// ======================================================================
// tcgen05-only helpers (emitted only in the arch-specific pass)
// ======================================================================
#if HAS_TCGEN05

__device__ __forceinline__ bool elect_one() {
    uint32_t p;
    asm volatile("{\n\t.reg .pred P;\n\telect.sync _|P, 0xFFFFFFFF;\n\tselp.b32 %0, 1, 0, P;\n\t}"
                 : "=r"(p));
    return p != 0;
}

#define MBAR_INIT(a, n) \
    asm volatile("mbarrier.init.shared.b64 [%0], %1;" :: "r"(a), "r"((uint32_t)(n)) : "memory")

#define MBAR_WAIT(a, ph) do {                                                   \
    uint32_t done_;                                                             \
    asm volatile("{\n\t.reg .pred P;\n\t"                                       \
        "mbarrier.try_wait.parity.acquire.cta.shared::cta.b64 P, [%1], %2;\n\t" \
        "selp.b32 %0, 1, 0, P;\n\t}"                                            \
        : "=r"(done_) : "r"(a), "r"((uint32_t)(ph)) : "memory");                \
    if (!done_) {                                                               \
        asm volatile("{\n\t.reg .pred P1;\n\t"                                  \
            "WL%=:\n\t"                                                         \
            "mbarrier.try_wait.parity.acquire.cta.shared::cta.b64 P1, [%0], %1, 0x989680;\n\t" \
            "@P1 bra.uni WD%=;\n\t"                                             \
            "bra.uni WL%=;\n\t"                                                 \
            "WD%=:\n\t}"                                                        \
            :: "r"(a), "r"((uint32_t)(ph)) : "memory");                         \
    }                                                                           \
} while (0)

#define MBAR_EXPECT_TX(a, bytes) \
    asm volatile("mbarrier.arrive.expect_tx.shared.b64 _, [%0], %1;" \
                 :: "r"(a), "r"((uint32_t)(bytes)) : "memory")

// cg2 TMA: data to MY smem; complete_tx to the LEADER CTA's barrier
// (bit 24 = Sm100MmaPeerBitMask cleared -> rank-0 of the pair).
#define TMA_2D_CG2(dst, map, cx, cy, mbar) \
    asm volatile("{\n\t.reg .b32 lb;\n\tand.b32 lb, %4, 0xFEFFFFFF;\n\t" \
        "cp.async.bulk.tensor.2d.cta_group::2.shared::cluster.global.tile.mbarrier::complete_tx::bytes " \
        "[%0], [%1, {%2, %3}], [lb];\n\t}" \
        :: "r"(dst), "l"(map), "r"((int)(cx)), "r"((int)(cy)), "r"(mbar) : "memory")

#define TC_ALLOC_CG2(sa, n) \
    asm volatile("tcgen05.alloc.cta_group::2.sync.aligned.shared::cta.b32 [%0], %1;" \
                 :: "r"(sa), "r"((uint32_t)(n)) : "memory")
#define TC_RELINQ_CG2() \
    asm volatile("tcgen05.relinquish_alloc_permit.cta_group::2.sync.aligned;")
#define TC_DEALLOC_CG2(t, n) \
    asm volatile("tcgen05.dealloc.cta_group::2.sync.aligned.b32 %0, %1;" \
                 :: "r"(t), "r"((uint32_t)(n)))
// cg2 commit, multicast to both pair CTAs' reuse barrier (same smem offset)
#define TC_COMMIT_MC_CG2(mb, mask) \
    asm volatile("tcgen05.commit.cta_group::2.mbarrier::arrive::one.shared::cluster.multicast::cluster.b64 [%0], %1;" \
                 :: "r"(mb), "h"((uint16_t)(mask)) : "memory")
#define TC_FENCE_AFTER() \
    asm volatile("tcgen05.fence::after_thread_sync;" ::: "memory")
#define TC_WAIT_LD() \
    asm volatile("tcgen05.wait::ld.sync.aligned;" ::: "memory")

#define CLUSTER_SYNC() do { \
    asm volatile("barrier.cluster.arrive.aligned;" ::: "memory"); \
    asm volatile("barrier.cluster.wait.aligned;" ::: "memory"); \
} while (0)

#define TC_LD_32X32B_X32(r, ta)                                                 \
    asm volatile(                                                               \
        "tcgen05.ld.sync.aligned.32x32b.x32.b32 "                               \
        "{%0, %1, %2, %3, %4, %5, %6, %7, "                                     \
        " %8, %9, %10, %11, %12, %13, %14, %15, "                               \
        " %16, %17, %18, %19, %20, %21, %22, %23, "                             \
        " %24, %25, %26, %27, %28, %29, %30, %31}, [%32];"                      \
        : "=r"((r)[0]),  "=r"((r)[1]),  "=r"((r)[2]),  "=r"((r)[3]),            \
          "=r"((r)[4]),  "=r"((r)[5]),  "=r"((r)[6]),  "=r"((r)[7]),            \
          "=r"((r)[8]),  "=r"((r)[9]),  "=r"((r)[10]), "=r"((r)[11]),           \
          "=r"((r)[12]), "=r"((r)[13]), "=r"((r)[14]), "=r"((r)[15]),           \
          "=r"((r)[16]), "=r"((r)[17]), "=r"((r)[18]), "=r"((r)[19]),           \
          "=r"((r)[20]), "=r"((r)[21]), "=r"((r)[22]), "=r"((r)[23]),           \
          "=r"((r)[24]), "=r"((r)[25]), "=r"((r)[26]), "=r"((r)[27]),           \
          "=r"((r)[28]), "=r"((r)[29]), "=r"((r)[30]), "=r"((r)[31])            \
        : "r"(ta))

// SS mma, cta_group::2, kind::tf32 (K=8 per dispatch, M=256 across the pair)
__device__ __forceinline__ void mma_tf32_cg2(uint32_t d, uint64_t ad, uint64_t bd,
                                             uint32_t idesc, uint32_t en) {
    asm volatile(
        "{\n\t.reg .pred p;\n\tsetp.ne.u32 p, %4, 0;\n\t"
        "tcgen05.mma.cta_group::2.kind::tf32 [%0], %1, %2, %3, "
        "{%5, %5, %5, %5, %5, %5, %5, %5}, p;\n\t}\n"
        :: "r"(d), "l"(ad), "l"(bd), "r"(idesc), "r"(en), "r"(0u) : "memory");
}

// SW128 K-major descriptor: layout=2, version=1, SBO=64, LBO=1
__device__ __forceinline__ uint64_t smem_desc_sw128(uint32_t addr) {
    return (2ull << 61) | (1ull << 46) | (64ull << 32) | (1ull << 16)
         | ((uint64_t)(addr >> 4) & 0x3FFF);
}

#endif  // HAS_TCGEN05

// ======================================================================
// cg2 tcgen05 tf32 GEMM: C[M,N] = act(A[M,K] @ B[N,K]^T + bias[N])
// Cluster (2,1,1): cg2 pairs MUST be adjacent along cluster X
// (CUTLASS 2sm constraint; (1,2,1) fails launch with "cluster
// misconfiguration"). Pair computes BM=256 (M=256 cg2 atom, A split
// 128/CTA) x BN=512 (two N=256 cg2 MMAs; B split 128 rows/CTA). BK=32.
// Per CTA per kt: A 16KB + B 32KB = 48KB -> 0.75 B/elem LTS traffic.
// 3-stage TMA ring; all complete_tx -> leader full barrier (96KB);
// leader MMAs + cg2 commit-multicast -> both reuse barriers gate refills.
// grid = (NROWS/128, N/512): M-tiles along X (paired), N-tiles along Y.
// ======================================================================
#define STAGE_BYTES  49152                       // A 16KB + B 32KB
#define GEMM_SMEM_BYTES (1024 + 3 * STAGE_BYTES) // 148480

template <int ACT, bool ROUND>
__global__ void __launch_bounds__(128, 1) __cluster_dims__(2, 1, 1)
gemm_tc(const __grid_constant__ CUtensorMap tmA,
        const __grid_constant__ CUtensorMap tmB,
        const float* __restrict__ bias, float* __restrict__ C,
        int N, int K) {
#if HAS_TCGEN05
    extern __shared__ char smem[];
    const uint32_t sbase = smem_addr_u32(smem);
    const int tid  = threadIdx.x;
    const int wid  = tid >> 5;
    const int lane = tid & 31;

    uint32_t rank;
    asm("mov.u32 %0, %%cluster_ctarank;" : "=r"(rank));

    // ctrl block: [0..4) tmem ptr, full[3] at +8/+16/+24 (leader-used),
    // reuse[3] at +32/+40/+48
    const uint32_t fullb0 = sbase + 8;
    const uint32_t reub0  = sbase + 32;
    const uint32_t tb = (sbase + 64 + 1023) & ~1023u;   // 1KB-aligned tile base
    const uint32_t aBase[3] = { tb, tb + STAGE_BYTES, tb + 2 * STAGE_BYTES };

    if (tid == 0) {
        #pragma unroll
        for (int s = 0; s < 3; s++) {
            MBAR_INIT(fullb0 + s * 8, 1);          // 1 arrive: leader's expect_tx
            MBAR_INIT(reub0 + s * 8, 1);           // 1 arrive: cg2 commit-mc
        }
    }
    if (wid == 0) { TC_ALLOC_CG2(sbase, 512); TC_RELINQ_CG2(); }
    __syncthreads();
    uint32_t tmem;
    asm volatile("ld.shared.b32 %0, [%1];" : "=r"(tmem) : "r"(sbase));

    // barriers + TMEM alloc visible pair-wide before any TMA/MMA
    CLUSTER_SYNC();

    const int bRowCTA = blockIdx.x * 128;          // this CTA's 128 A/D rows
    const int bCol = blockIdx.y * 512;
    const int KT = K >> 5;
    const bool leader = (rank == 0);

    if (wid == 0 && elect_one()) {
        auto issue = [&](int s, int k0) {
            const uint32_t fb = fullb0 + s * 8;
            if (leader) MBAR_EXPECT_TX(fb, 2 * 49152u);   // pair total 96KB
            // A: my 128 M-rows
            TMA_2D_CG2(aBase[s], &tmA, k0, bRowCTA, fb);
            // B halves: MMA h reads N-rows [h*256 + rank*128, +128) from my smem
            TMA_2D_CG2(aBase[s] + 16384, &tmB, k0, bCol + (int)rank * 128, fb);
            TMA_2D_CG2(aBase[s] + 32768, &tmB, k0, bCol + 256 + (int)rank * 128, fb);
        };

        // prologue: stages 0..2
        issue(0, 0);
        issue(1, 32);
        issue(2, 64);

        int ff[3] = { 0, 0, 0 };
        int rr[3] = { 0, 0, 0 };
        // idesc: dtype=F32(1<<4), atype=btype=TF32(2), N=256, M=256 (cg2)
        const uint32_t IDESC = (1u << 4) | (2u << 7) | (2u << 10)
                             | ((256u / 8) << 17) | ((256u / 16) << 24);

        for (int kt = 0; kt < KT; kt++) {
            const int s = kt - (kt / 3) * 3;       // kt % 3
            if (leader) {
                MBAR_WAIT(fullb0 + s * 8, ff[s]); ff[s] ^= 1;
                uint64_t aD = smem_desc_sw128(aBase[s]);
                #pragma unroll
                for (int h = 0; h < 2; h++) {
                    uint64_t bD = smem_desc_sw128(aBase[s] + 16384 + h * 16384);
                    #pragma unroll
                    for (int ks = 0; ks < 4; ks++)
                        mma_tf32_cg2(tmem + h * 256,
                                     aD + ks * 2,
                                     bD + ks * 2,
                                     IDESC,
                                     (kt > 0 || ks > 0) ? 1u : 0u);
                }
                TC_COMMIT_MC_CG2(reub0 + s * 8, 0x3);
            }

            if (kt + 3 < KT) {
                // pair-wide MMAs of round kt must retire before stage s refill
                MBAR_WAIT(reub0 + s * 8, rr[s]); rr[s] ^= 1;
                issue(s, (kt + 3) * 32);
            }
        }

        // final: wait the last commit (commits complete in order)
        const int sl = (KT - 1) - ((KT - 1) / 3) * 3;
        MBAR_WAIT(reub0 + sl * 8, rr[sl]);
    }
    TC_FENCE_AFTER();
    __syncthreads();

    // ---- epilogue: my TMEM 128 rows x 512 cols -> bias/act/round -> smem
    // transpose -> coalesced STG. 16 chunks of 32 cols.
    float* ep = (float*)(smem + (tb - sbase));    // 2 x [128][33] staging
    for (int ch = 0; ch < 16; ch++) {
        uint32_t dreg[32];
        TC_LD_32X32B_X32(dreg, tmem + ch * 32);
        TC_WAIT_LD();
        float* buf = ep + (ch & 1) * (128 * 33);
        #pragma unroll
        for (int j = 0; j < 32; j++) {
            float v = __uint_as_float(dreg[j]) + bias[bCol + ch * 32 + j];
            if (ACT == ACT_RELU) v = fmaxf(v, 0.f);
            if (ACT == ACT_TANH) v = tanh_fast(v);
            if (ROUND) v = tf32_rna(v);
            buf[tid * 33 + j] = v;
        }
        __syncthreads();
        #pragma unroll
        for (int jj = 0; jj < 32; jj++) {
            int r = wid + jj * 4;
            C[(size_t)(bRowCTA + r) * N + bCol + ch * 32 + lane] = buf[r * 33 + lane];
        }
        __syncthreads();
    }
    if (wid == 0) TC_DEALLOC_CG2(tmem, 512);
    // no CTA exits while peer traffic (TMA complete_tx / commit-mc / peer
    // smem reads by MMA) may still target it
    CLUSTER_SYNC();
#else
    (void)bias; (void)C; (void)N; (void)K;
#endif
}

// ======================================================================
// Fallback mma.sync tf32 GEMM (round-4 proven kernel).
// No-op body in the arch-specific pass (tcgen05 kernel runs instead).
// ======================================================================
template <int ACT, bool ROUND>
__global__ __launch_bounds__(256) void gemm_fb(const float* __restrict__ A,
                                               const float* __restrict__ B,
                                               const float* __restrict__ bias,
                                               float* __restrict__ C,
                                               int M, int N, int K) {
#if !HAS_TCGEN05
    __shared__ float As[2][128][20];
    __shared__ float Bs[2][128][20];

    const int tid  = threadIdx.x;
    const int bRow = blockIdx.y * 128;
    const int bCol = blockIdx.x * 128;
    const int warp = tid >> 5;
    const int lane = tid & 31;
    const int wRow = (warp >> 2) * 64;
    const int wCol = (warp & 3) * 32;
    const int g = lane >> 2;
    const int t = lane & 3;

    float acc[4][4][4];
    #pragma unroll
    for (int i = 0; i < 4; i++)
        #pragma unroll
        for (int j = 0; j < 4; j++)
            #pragma unroll
            for (int r = 0; r < 4; r++) acc[i][j][r] = 0.f;

    auto load_stage = [&](int s, int kt) {
        int k0 = kt * 16;
        #pragma unroll
        for (int it = 0; it < 2; it++) {
            int idx = tid + it * 256;
            int r = idx >> 2;
            int c = (idx & 3) << 2;
            const float* ga = A + (size_t)(bRow + r) * K + k0 + c;
            unsigned da = (unsigned)__cvta_generic_to_shared(&As[s][r][c]);
            CP_ASYNC16(da, ga);
            const float* gb = B + (size_t)(bCol + r) * K + k0 + c;
            unsigned db = (unsigned)__cvta_generic_to_shared(&Bs[s][r][c]);
            CP_ASYNC16(db, gb);
        }
    };

    const int KT = K >> 4;
    load_stage(0, 0); CP_COMMIT();
    load_stage(1, 1); CP_COMMIT();
    CP_WAIT1();
    __syncthreads();

    for (int kt = 0; kt < KT; kt++) {
        int s = kt & 1;
        #pragma unroll
        for (int ks = 0; ks < 2; ks++) {
            int k0 = ks * 8;
            unsigned af[4][4];
            unsigned bf[4][2];
            #pragma unroll
            for (int mt = 0; mt < 4; mt++) {
                int r = wRow + mt * 16 + g;
                af[mt][0] = __float_as_uint(As[s][r][k0 + t]);
                af[mt][1] = __float_as_uint(As[s][r + 8][k0 + t]);
                af[mt][2] = __float_as_uint(As[s][r][k0 + t + 4]);
                af[mt][3] = __float_as_uint(As[s][r + 8][k0 + t + 4]);
            }
            #pragma unroll
            for (int nt = 0; nt < 4; nt++) {
                int c = wCol + nt * 8 + g;
                bf[nt][0] = __float_as_uint(Bs[s][c][k0 + t]);
                bf[nt][1] = __float_as_uint(Bs[s][c][k0 + t + 4]);
            }
            #pragma unroll
            for (int mt = 0; mt < 4; mt++)
                #pragma unroll
                for (int nt = 0; nt < 4; nt++) {
                    asm volatile(
                        "mma.sync.aligned.m16n8k8.row.col.f32.tf32.tf32.f32 "
                        "{%0,%1,%2,%3}, {%4,%5,%6,%7}, {%8,%9}, {%0,%1,%2,%3};"
                        : "+f"(acc[mt][nt][0]), "+f"(acc[mt][nt][1]),
                          "+f"(acc[mt][nt][2]), "+f"(acc[mt][nt][3])
                        : "r"(af[mt][0]), "r"(af[mt][1]), "r"(af[mt][2]), "r"(af[mt][3]),
                          "r"(bf[nt][0]), "r"(bf[nt][1]));
                }
        }
        __syncthreads();
        if (kt + 2 < KT) load_stage(s, kt + 2);
        CP_COMMIT();
        CP_WAIT1();
        __syncthreads();
    }

    #pragma unroll
    for (int mt = 0; mt < 4; mt++) {
        int r0 = bRow + wRow + mt * 16 + g;
        #pragma unroll
        for (int nt = 0; nt < 4; nt++) {
            int c0 = bCol + wCol + nt * 8 + t * 2;
            float bv0 = bias[c0], bv1 = bias[c0 + 1];
            float v0 = acc[mt][nt][0] + bv0;
            float v1 = acc[mt][nt][1] + bv1;
            float v2 = acc[mt][nt][2] + bv0;
            float v3 = acc[mt][nt][3] + bv1;
            if (ACT == ACT_RELU) {
                v0 = fmaxf(v0, 0.f); v1 = fmaxf(v1, 0.f);
                v2 = fmaxf(v2, 0.f); v3 = fmaxf(v3, 0.f);
            } else if (ACT == ACT_TANH) {
                v0 = tanh_fast(v0); v1 = tanh_fast(v1);
                v2 = tanh_fast(v2); v3 = tanh_fast(v3);
            }
            if (ROUND) {
                v0 = tf32_rna(v0); v1 = tf32_rna(v1);
                v2 = tf32_rna(v2); v3 = tf32_rna(v3);
            }
            float2 p0; p0.x = v0; p0.y = v1;
            float2 p1; p1.x = v2; p1.y = v3;
            *(float2*)(C + (size_t)r0 * N + c0)       = p0;
            *(float2*)(C + (size_t)(r0 + 8) * N + c0) = p1;
        }
    }
#else
    (void)A; (void)B; (void)bias; (void)C; (void)M; (void)N; (void)K;
#endif
}

// ---------------- host-side tensormap builder ----------------
typedef CUresult (*cuTensorMapEncodeTiled_t)(
    CUtensorMap*, CUtensorMapDataType, cuuint32_t, void*,
    const cuuint64_t*, const cuuint64_t*, const cuuint32_t*, const cuuint32_t*,
    CUtensorMapInterleave, CUtensorMapSwizzle, CUtensorMapL2promotion,
    CUtensorMapFloatOOBfill);

static cuTensorMapEncodeTiled_t get_enc() {
    static cuTensorMapEncodeTiled_t fn = nullptr;
    if (!fn) {
        cudaDriverEntryPointQueryResult st;
#if CUDART_VERSION >= 12050
        cudaGetDriverEntryPointByVersion("cuTensorMapEncodeTiled", (void**)&fn,
                                         12000, cudaEnableDefault, &st);
#else
        cudaGetDriverEntryPoint("cuTensorMapEncodeTiled", (void**)&fn,
                                cudaEnableDefault, &st);
#endif
    }
    return fn;
}

// 2D map over row-major [rows, K] float matrix; box (32 cols, 128 rows), SW128
static void make_map(CUtensorMap* m, float* base, int K, int rows) {
    cuuint64_t dims[2]    = { (cuuint64_t)K, (cuuint64_t)rows };
    cuuint64_t strides[1] = { (cuuint64_t)K * 4 };
    cuuint32_t box[2]     = { 32u, 128u };
    cuuint32_t es[2]      = { 1u, 1u };
    cuTensorMapEncodeTiled_t enc = get_enc();
    if (enc)
        enc(m, CU_TENSOR_MAP_DATA_TYPE_FLOAT32, 2, base, dims, strides, box, es,
            CU_TENSOR_MAP_INTERLEAVE_NONE, CU_TENSOR_MAP_SWIZZLE_128B,
            CU_TENSOR_MAP_L2_PROMOTION_L2_128B, CU_TENSOR_MAP_FLOAT_OOB_FILL_NONE);
}

// ---------------- launch ----------------
extern "C" void kernel_launch(void* const* d_in, const int* in_sizes, int n_in,
                              void* d_out, int out_size) {
    (void)in_sizes; (void)n_in; (void)out_size;
    const float* x  = (const float*)d_in[0];
    const float* Wg = (const float*)d_in[1];
    const float* We = (const float*)d_in[2];
    const float* be = (const float*)d_in[3];
    const float* W1 = (const float*)d_in[4];
    const float* b1 = (const float*)d_in[5];
    const float* W2 = (const float*)d_in[6];
    const float* b2 = (const float*)d_in[7];
    const float* Wo = (const float*)d_in[8];
    const float* bo = (const float*)d_in[9];
    float* out = (float*)d_out;

    float *A0, *actA, *actB, *Wef, *W1c, *W2c, *Woc, *beS;
    cudaGetSymbolAddress((void**)&A0,  g_A0);
    cudaGetSymbolAddress((void**)&actA, g_actA);
    cudaGetSymbolAddress((void**)&actB, g_actB);
    cudaGetSymbolAddress((void**)&Wef, g_Wef);
    cudaGetSymbolAddress((void**)&W1c, g_W1c);
    cudaGetSymbolAddress((void**)&W2c, g_W2c);
    cudaGetSymbolAddress((void**)&Woc, g_Woc);
    cudaGetSymbolAddress((void**)&beS, g_beS);

    // tensormaps (host-built, passed by value; snapshot at graph capture)
    CUtensorMap mA0{}, mAA{}, mAB{}, mWe{}, mW1{}, mW2{}, mWo{};
    make_map(&mA0, A0,  DIN,  NROWS);
    make_map(&mAA, actA, 1024, NROWS);
    make_map(&mAB, actB, 1024, NROWS);
    make_map(&mWe, Wef, DIN,  ESZ);
    make_map(&mW1, W1c, ESZ,  H1SZ);
    make_map(&mW2, W2c, H1SZ, H2SZ);
    make_map(&mWo, Woc, H2SZ, OSZ);

    cudaFuncSetAttribute(gemm_tc<ACT_RELU, true>,
                         cudaFuncAttributeMaxDynamicSharedMemorySize, GEMM_SMEM_BYTES);
    cudaFuncSetAttribute(gemm_tc<ACT_TANH, true>,
                         cudaFuncAttributeMaxDynamicSharedMemorySize, GEMM_SMEM_BYTES);
    cudaFuncSetAttribute(gemm_tc<ACT_NONE, false>,
                         cudaFuncAttributeMaxDynamicSharedMemorySize, GEMM_SMEM_BYTES);

    // weight prep (cheap, idempotent)
    prep_we<<<(ESZ * DIN + 255) / 256, 256>>>(We, Wef);
    prep_cvt<<<(H1SZ * ESZ + 255) / 256, 256>>>(W1, W1c, H1SZ * ESZ);
    prep_cvt<<<(H2SZ * H1SZ + 255) / 256, 256>>>(W2, W2c, H2SZ * H1SZ);
    prep_cvt<<<(OSZ * H2SZ + 255) / 256, 256>>>(Wo, Woc, OSZ * H2SZ);
    prep_besum<<<(ESZ + 255) / 256, 256>>>(be, beS);

    // gates + gated/rounded A0
    gate_kernel<<<NROWS / 8, 256>>>(x, Wg, A0);

    // Fallback chain (no-op bodies when the sm_103a-specific cubin is loaded)
    gemm_fb<ACT_RELU, true><<<dim3(ESZ / 128, NROWS / 128), 256>>>(A0, Wef, beS, actA, NROWS, ESZ, DIN);
    gemm_fb<ACT_TANH, true><<<dim3(H1SZ / 128, NROWS / 128), 256>>>(actA, W1c, b1, actB, NROWS, H1SZ, ESZ);
    gemm_fb<ACT_TANH, true><<<dim3(H2SZ / 128, NROWS / 128), 256>>>(actB, W2c, b2, actA, NROWS, H2SZ, H1SZ);
    gemm_fb<ACT_NONE, false><<<dim3(OSZ / 128, NROWS / 128), 256>>>(actA, Woc, bo, out, NROWS, OSZ, H2SZ);

    // cg2 tcgen05 chain (no-op bodies in the generic pass):
    // cluster (2,1,1): M-tiles along X (paired), N-tiles along Y.
    // grid = (NROWS/128, N/512); pair tile = 256x512.
    gemm_tc<ACT_RELU, true><<<dim3(NROWS / 128, ESZ / 512), 128, GEMM_SMEM_BYTES>>>(
        mA0, mWe, beS, actA, ESZ, DIN);
    gemm_tc<ACT_TANH, true><<<dim3(NROWS / 128, H1SZ / 512), 128, GEMM_SMEM_BYTES>>>(
        mAA, mW1, b1, actB, H1SZ, ESZ);
    gemm_tc<ACT_TANH, true><<<dim3(NROWS / 128, H2SZ / 512), 128, GEMM_SMEM_BYTES>>>(
        mAB, mW2, b2, actA, H2SZ, H1SZ);
    gemm_tc<ACT_NONE, false><<<dim3(NROWS / 128, OSZ / 512), 128, GEMM_SMEM_BYTES>>>(
        mAA, mWo, bo, out, OSZ, H2SZ);
}

// round 16
// speedup vs baseline: 1.1903x; 1.1805x over previous
#include <cuda_runtime.h>
#include <cstdint>

// ---------------- problem dims ----------------
#define NROWS  32768      // B*T = 64*512
#define DIN    1536       // L*IN
#define INSZ   512
#define ESZ    1024
#define H1SZ   1024
#define H2SZ   1024
#define OSZ    512

// tcgen05 is arch-specific: only available in the sm_103a/sm_100a cubin pass.
#if defined(__CUDA_ARCH__) && (defined(__CUDA_ARCH_FEAT_SM103_ALL) || defined(__CUDA_ARCH_FEAT_SM100_ALL) || (defined(__CUDA_ARCH_SPECIFIC__) && (__CUDA_ARCH_SPECIFIC__ >= 1000)))
#define HAS_TCGEN05 1
#else
#define HAS_TCGEN05 0
#endif

// ---------------- scratch (device globals; allocation-free) ----------------
__device__ float g_A0[(size_t)NROWS * DIN];     // gated, tf32-rounded input
__device__ float g_actA[(size_t)NROWS * 1024];  // ping
__device__ float g_actB[(size_t)NROWS * 1024];  // pong
__device__ float g_Wef[(size_t)ESZ * DIN];      // flattened+tf32 We  [E, D]
__device__ float g_W1c[(size_t)H1SZ * ESZ];
__device__ float g_W2c[(size_t)H2SZ * H1SZ];
__device__ float g_Woc[(size_t)OSZ * H2SZ];
__device__ float g_beS[ESZ];

// ---------------- helpers ----------------
__device__ __forceinline__ float tf32_rna(float x) {
    uint32_t u;
    asm("cvt.rna.tf32.f32 %0, %1;" : "=r"(u) : "f"(x));
    return __uint_as_float(u);
}

__device__ __forceinline__ uint32_t smem_addr_u32(const void* p) {
    uint32_t a;
    asm("{ .reg .u64 t; cvta.to.shared.u64 t, %1; cvt.u32.u64 %0, t; }"
        : "=r"(a) : "l"(p));
    return a;
}

// HW tanh (MUFU.TANH, sm_75+): 1 instruction vs ~30 FMA for the rational
// approx. Rel err <= 2^-11 per value; downstream K=1024 GEMM sums average
// the quasi-random per-value errors down to ~2e-5 contribution.
__device__ __forceinline__ float tanh_hw(float x) {
    float y;
    asm("tanh.approx.f32 %0, %1;" : "=f"(y) : "f"(x));
    return y;
}

#define CP_ASYNC16(dst, src) \
    asm volatile("cp.async.cg.shared.global [%0], [%1], 16;" :: "r"(dst), "l"(src))
#define CP_COMMIT()  asm volatile("cp.async.commit_group;" ::: "memory")
#define CP_WAIT0()   asm volatile("cp.async.wait_group 0;" ::: "memory")
#define CP_WAIT1()   asm volatile("cp.async.wait_group 1;" ::: "memory")

// ---------------- weight prep ----------------
__global__ void prep_we(const float* __restrict__ We, float* __restrict__ Wef) {
    int idx = blockIdx.x * blockDim.x + threadIdx.x;
    if (idx >= ESZ * DIN) return;
    int e = idx / DIN;
    int d = idx - e * DIN;
    int l = d >> 9;
    int i = d & 511;
    Wef[idx] = tf32_rna(We[(size_t)l * ESZ * INSZ + (size_t)e * INSZ + i]);
}

__global__ void prep_cvt(const float* __restrict__ src, float* __restrict__ dst, int n) {
    int idx = blockIdx.x * blockDim.x + threadIdx.x;
    if (idx < n) dst[idx] = tf32_rna(src[idx]);
}

__global__ void prep_besum(const float* __restrict__ be, float* __restrict__ beS) {
    int i = blockIdx.x * blockDim.x + threadIdx.x;
    if (i < ESZ) beS[i] = be[i] + be[ESZ + i] + be[2 * ESZ + i];
}

// ---------------- gate kernel ----------------
__global__ __launch_bounds__(256) void gate_kernel(const float* __restrict__ x,
                                                   const float* __restrict__ Wg,
                                                   float* __restrict__ A0) {
    __shared__ float4 sWg[3 * 384];
    const float4* Wg4 = (const float4*)Wg;
    for (int i = threadIdx.x; i < 3 * 384; i += 256) sWg[i] = Wg4[i];
    __syncthreads();

    int warp = threadIdx.x >> 5;
    int lane = threadIdx.x & 31;
    size_t row = (size_t)blockIdx.x * 8 + warp;
    const float4* xr = (const float4*)(x + row * DIN);

    float a0 = 0.f, a1 = 0.f, a2 = 0.f;
    for (int i = lane; i < 384; i += 32) {
        float4 v = xr[i];
        float4 w0 = sWg[i], w1 = sWg[384 + i], w2 = sWg[768 + i];
        a0 += v.x * w0.x + v.y * w0.y + v.z * w0.z + v.w * w0.w;
        a1 += v.x * w1.x + v.y * w1.y + v.z * w1.z + v.w * w1.w;
        a2 += v.x * w2.x + v.y * w2.y + v.z * w2.z + v.w * w2.w;
    }
    #pragma unroll
    for (int off = 16; off; off >>= 1) {
        a0 += __shfl_xor_sync(0xffffffffu, a0, off);
        a1 += __shfl_xor_sync(0xffffffffu, a1, off);
        a2 += __shfl_xor_sync(0xffffffffu, a2, off);
    }
    float g0 = 1.f / (1.f + expf(-a0));
    float g1 = 1.f / (1.f + expf(-a1));
    float g2 = 1.f / (1.f + expf(-a2));

    float4* ar = (float4*)(A0 + row * DIN);
    for (int i = lane; i < 384; i += 32) {
        float4 v = xr[i];
        float gv = (i < 128) ? g0 : ((i < 256) ? g1 : g2);
        float4 o;
        o.x = tf32_rna(v.x * gv);
        o.y = tf32_rna(v.y * gv);
        o.z = tf32_rna(v.z * gv);
        o.w = tf32_rna(v.w * gv);
        ar[i] = o;
    }
}

#define ACT_NONE 0
#define ACT_RELU 1
#define ACT_TANH 2

// ======================================================================
// tcgen05-only helpers (emitted only in the arch-specific pass)
// ======================================================================
#if HAS_TCGEN05

__device__ __forceinline__ bool elect_one() {
    uint32_t p;
    asm volatile("{\n\t.reg .pred P;\n\telect.sync _|P, 0xFFFFFFFF;\n\tselp.b32 %0, 1, 0, P;\n\t}"
                 : "=r"(p));
    return p != 0;
}

#define MBAR_INIT(a) \
    asm volatile("mbarrier.init.shared.b64 [%0], 1;" :: "r"(a) : "memory")

#define MBAR_WAIT(a, ph) do {                                                   \
    uint32_t done_;                                                             \
    asm volatile("{\n\t.reg .pred P;\n\t"                                       \
        "mbarrier.try_wait.parity.acquire.cta.shared::cta.b64 P, [%1], %2;\n\t" \
        "selp.b32 %0, 1, 0, P;\n\t}"                                            \
        : "=r"(done_) : "r"(a), "r"((uint32_t)(ph)) : "memory");                \
    if (!done_) {                                                               \
        asm volatile("{\n\t.reg .pred P1;\n\t"                                  \
            "WL%=:\n\t"                                                         \
            "mbarrier.try_wait.parity.acquire.cta.shared::cta.b64 P1, [%0], %1, 0x989680;\n\t" \
            "@P1 bra.uni WD%=;\n\t"                                             \
            "bra.uni WL%=;\n\t"                                                 \
            "WD%=:\n\t}"                                                        \
            :: "r"(a), "r"((uint32_t)(ph)) : "memory");                         \
    }                                                                           \
} while (0)

#define TC_ALLOC(sa, n) \
    asm volatile("tcgen05.alloc.cta_group::1.sync.aligned.shared::cta.b32 [%0], %1;" \
                 :: "r"(sa), "r"((uint32_t)(n)) : "memory")
#define TC_RELINQ() \
    asm volatile("tcgen05.relinquish_alloc_permit.cta_group::1.sync.aligned;")
#define TC_DEALLOC(t, n) \
    asm volatile("tcgen05.dealloc.cta_group::1.sync.aligned.b32 %0, %1;" \
                 :: "r"(t), "r"((uint32_t)(n)))
#define TC_COMMIT(mb) \
    asm volatile("tcgen05.commit.cta_group::1.mbarrier::arrive::one.shared::cluster.b64 [%0];" \
                 :: "r"(mb) : "memory")
#define TC_FENCE_AFTER() \
    asm volatile("tcgen05.fence::after_thread_sync;" ::: "memory")
#define TC_WAIT_LD() \
    asm volatile("tcgen05.wait::ld.sync.aligned;" ::: "memory")

#define TC_LD_32X32B_X32(r, ta)                                                 \
    asm volatile(                                                               \
        "tcgen05.ld.sync.aligned.32x32b.x32.b32 "                               \
        "{%0, %1, %2, %3, %4, %5, %6, %7, "                                     \
        " %8, %9, %10, %11, %12, %13, %14, %15, "                               \
        " %16, %17, %18, %19, %20, %21, %22, %23, "                             \
        " %24, %25, %26, %27, %28, %29, %30, %31}, [%32];"                      \
        : "=r"((r)[0]),  "=r"((r)[1]),  "=r"((r)[2]),  "=r"((r)[3]),            \
          "=r"((r)[4]),  "=r"((r)[5]),  "=r"((r)[6]),  "=r"((r)[7]),            \
          "=r"((r)[8]),  "=r"((r)[9]),  "=r"((r)[10]), "=r"((r)[11]),           \
          "=r"((r)[12]), "=r"((r)[13]), "=r"((r)[14]), "=r"((r)[15]),           \
          "=r"((r)[16]), "=r"((r)[17]), "=r"((r)[18]), "=r"((r)[19]),           \
          "=r"((r)[20]), "=r"((r)[21]), "=r"((r)[22]), "=r"((r)[23]),           \
          "=r"((r)[24]), "=r"((r)[25]), "=r"((r)[26]), "=r"((r)[27]),           \
          "=r"((r)[28]), "=r"((r)[29]), "=r"((r)[30]), "=r"((r)[31])            \
        : "r"(ta))

// SS mma, cta_group::1, kind::tf32 (K=8 per dispatch)
__device__ __forceinline__ void mma_tf32(uint32_t d, uint64_t ad, uint64_t bd,
                                         uint32_t idesc, uint32_t en) {
    asm volatile(
        "{\n\t.reg .pred p;\n\tsetp.ne.u32 p, %4, 0;\n\t"
        "tcgen05.mma.cta_group::1.kind::tf32 [%0], %1, %2, %3, {%5, %5, %5, %5}, p;\n\t}\n"
        :: "r"(d), "l"(ad), "l"(bd), "r"(idesc), "r"(en), "r"(0u) : "memory");
}

// SW128 K-major descriptor: layout=2, version=1, SBO=64, LBO=1
__device__ __forceinline__ uint64_t smem_desc_sw128(uint32_t addr) {
    return (2ull << 61) | (1ull << 46) | (64ull << 32) | (1ull << 16)
         | ((uint64_t)(addr >> 4) & 0x3FFF);
}

#endif  // HAS_TCGEN05

// ======================================================================
// tcgen05 tf32 GEMM: C[M,N] = act(A[M,K] @ B[N,K]^T + bias[N])
// BM=256 (2x M=128 halves), BN=256, BK=32, 128 threads, 3-stage cp.async ring.
// D: half0 -> TMEM cols 0-255, half1 -> cols 256-511.
// (Round-8 proven structure; only the tanh epilogue changed to MUFU.)
// ======================================================================
#define STAGE_BYTES  65536                       // A 32KB + B 32KB
#define GEMM_SMEM_BYTES (1024 + 3 * STAGE_BYTES) // 197632

template <int ACT, bool ROUND>
__global__ void __launch_bounds__(128, 1)
gemm_tc(const float* __restrict__ A, const float* __restrict__ B,
        const float* __restrict__ bias, float* __restrict__ C,
        int N, int K) {
#if HAS_TCGEN05
    extern __shared__ char smem[];
    const uint32_t sbase = smem_addr_u32(smem);
    const int tid  = threadIdx.x;
    const int wid  = tid >> 5;
    const int lane = tid & 31;

    const uint32_t mb[3] = { sbase + 8, sbase + 16, sbase + 24 };
    const uint32_t tb = (sbase + 32 + 1023) & ~1023u;   // 1KB-aligned tile base
    // stage s: A at tb + s*64KB (two 16KB M-halves), B at +32KB
    const uint32_t aBase[3] = { tb, tb + STAGE_BYTES, tb + 2 * STAGE_BYTES };

    if (tid == 0) { MBAR_INIT(mb[0]); MBAR_INIT(mb[1]); MBAR_INIT(mb[2]); }
    if (wid == 0) { TC_ALLOC(sbase, 512); TC_RELINQ(); }
    __syncthreads();
    uint32_t tmem;
    asm volatile("ld.shared.b32 %0, [%1];" : "=r"(tmem) : "r"(sbase));

    const int bRow = blockIdx.y * 256;
    const int bCol = blockIdx.x * 256;
    const int KT = K >> 5;

    const float* Arow = A + (size_t)bRow * K;
    const float* Brow = B + (size_t)bCol * K;

    auto load_stage = [&](int s, int k0) {
        const uint32_t aB = aBase[s];
        const uint32_t bB = aBase[s] + 32768;
        #pragma unroll
        for (int m = 0; m < 16; m++) {             // A: 256 rows x 128B
            int i = tid + m * 128;
            int r = i >> 3, c = i & 7;
            uint32_t off = (uint32_t)(r * 128 + c * 16);
            uint32_t dst = aB + (off ^ ((off >> 3) & 0x70));
            CP_ASYNC16(dst, Arow + (size_t)r * K + k0 + c * 4);
        }
        #pragma unroll
        for (int m = 0; m < 16; m++) {             // B: 256 rows x 128B
            int i = tid + m * 128;
            int r = i >> 3, c = i & 7;
            uint32_t off = (uint32_t)(r * 128 + c * 16);
            uint32_t dst = bB + (off ^ ((off >> 3) & 0x70));
            CP_ASYNC16(dst, Brow + (size_t)r * K + k0 + c * 4);
        }
    };

    // prologue: stages 0,1
    load_stage(0, 0);
    CP_COMMIT();
    load_stage(1, 32);
    CP_COMMIT();

    int ph[3] = { 0, 0, 0 };
    // idesc: dtype=F32(1<<4), atype=btype=TF32(2), N=256, M=128
    const uint32_t IDESC = (1u << 4) | (2u << 7) | (2u << 10)
                         | ((256u / 8) << 17) | ((128u / 16) << 24);

    for (int kt = 0; kt < KT; kt++) {
        const int s = kt - (kt / 3) * 3;           // kt % 3
        if (kt + 1 < KT) { CP_WAIT1(); }           // stage s is second-newest group
        else             { CP_WAIT0(); }           // last iter: stage s is newest
        asm volatile("fence.proxy.async.shared::cta;" ::: "memory");
        __syncthreads();

        if (wid == 0 && elect_one()) {
            uint64_t bD = smem_desc_sw128(aBase[s] + 32768);
            #pragma unroll
            for (int h = 0; h < 2; h++) {
                uint64_t aD = smem_desc_sw128(aBase[s] + h * 16384);
                #pragma unroll
                for (int ks = 0; ks < 4; ks++)
                    mma_tf32(tmem + h * 256,
                             aD + ks * 2,
                             bD + ks * 2,
                             IDESC,
                             (kt > 0 || ks > 0) ? 1u : 0u);
            }
            TC_COMMIT(mb[s]);
        }

        if (kt + 2 < KT) {
            const int j = (kt + 2) - ((kt + 2) / 3) * 3;   // (kt+2) % 3
            if (kt >= 1) { MBAR_WAIT(mb[j], ph[j]); ph[j] ^= 1; }   // MMA(kt-1) done with buf j
            load_stage(j, (kt + 2) * 32);
            CP_COMMIT();
        }
    }

    // wait for the final commit
    {
        const int jl = (KT - 1) - ((KT - 1) / 3) * 3;
        MBAR_WAIT(mb[jl], ph[jl]);
    }
    TC_FENCE_AFTER();
    __syncthreads();

    // ---- epilogue: TMEM -> (bias, act, round) -> smem transpose -> coalesced STG
    // D layout: thread tid holds row (h*128 + tid), cols ch*32..+31 at tmem + h*256 + ch*32
    float* ep = (float*)(smem + (tb - sbase));    // 2 x [128][33] staging (reuses tiles)
    #pragma unroll 1
    for (int h = 0; h < 2; h++) {
        for (int ch = 0; ch < 8; ch++) {
            uint32_t dreg[32];
            TC_LD_32X32B_X32(dreg, tmem + h * 256 + ch * 32);
            TC_WAIT_LD();
            float* buf = ep + (ch & 1) * (128 * 33);
            #pragma unroll
            for (int j = 0; j < 32; j++) {
                float v = __uint_as_float(dreg[j]) + bias[bCol + ch * 32 + j];
                if (ACT == ACT_RELU) v = fmaxf(v, 0.f);
                if (ACT == ACT_TANH) v = tanh_hw(v);
                if (ROUND) v = tf32_rna(v);
                buf[tid * 33 + j] = v;
            }
            __syncthreads();
            #pragma unroll
            for (int jj = 0; jj < 32; jj++) {
                int r = wid + jj * 4;
                C[(size_t)(bRow + h * 128 + r) * N + bCol + ch * 32 + lane]
                    = buf[r * 33 + lane];
            }
        }
        __syncthreads();
    }
    if (wid == 0) TC_DEALLOC(tmem, 512);
#else
    (void)A; (void)B; (void)bias; (void)C; (void)N; (void)K;
#endif
}

// ======================================================================
// Fallback mma.sync tf32 GEMM (round-4 proven kernel).
// No-op body in the arch-specific pass (tcgen05 kernel runs instead).
// ======================================================================
template <int ACT, bool ROUND>
__global__ __launch_bounds__(256) void gemm_fb(const float* __restrict__ A,
                                               const float* __restrict__ B,
                                               const float* __restrict__ bias,
                                               float* __restrict__ C,
                                               int M, int N, int K) {
#if !HAS_TCGEN05
    __shared__ float As[2][128][20];
    __shared__ float Bs[2][128][20];

    const int tid  = threadIdx.x;
    const int bRow = blockIdx.y * 128;
    const int bCol = blockIdx.x * 128;
    const int warp = tid >> 5;
    const int lane = tid & 31;
    const int wRow = (warp >> 2) * 64;
    const int wCol = (warp & 3) * 32;
    const int g = lane >> 2;
    const int t = lane & 3;

    float acc[4][4][4];
    #pragma unroll
    for (int i = 0; i < 4; i++)
        #pragma unroll
        for (int j = 0; j < 4; j++)
            #pragma unroll
            for (int r = 0; r < 4; r++) acc[i][j][r] = 0.f;

    auto load_stage = [&](int s, int kt) {
        int k0 = kt * 16;
        #pragma unroll
        for (int it = 0; it < 2; it++) {
            int idx = tid + it * 256;
            int r = idx >> 2;
            int c = (idx & 3) << 2;
            const float* ga = A + (size_t)(bRow + r) * K + k0 + c;
            unsigned da = (unsigned)__cvta_generic_to_shared(&As[s][r][c]);
            CP_ASYNC16(da, ga);
            const float* gb = B + (size_t)(bCol + r) * K + k0 + c;
            unsigned db = (unsigned)__cvta_generic_to_shared(&Bs[s][r][c]);
            CP_ASYNC16(db, gb);
        }
    };

    const int KT = K >> 4;
    load_stage(0, 0); CP_COMMIT();
    load_stage(1, 1); CP_COMMIT();
    CP_WAIT1();
    __syncthreads();

    for (int kt = 0; kt < KT; kt++) {
        int s = kt & 1;
        #pragma unroll
        for (int ks = 0; ks < 2; ks++) {
            int k0 = ks * 8;
            unsigned af[4][4];
            unsigned bf[4][2];
            #pragma unroll
            for (int mt = 0; mt < 4; mt++) {
                int r = wRow + mt * 16 + g;
                af[mt][0] = __float_as_uint(As[s][r][k0 + t]);
                af[mt][1] = __float_as_uint(As[s][r + 8][k0 + t]);
                af[mt][2] = __float_as_uint(As[s][r][k0 + t + 4]);
                af[mt][3] = __float_as_uint(As[s][r + 8][k0 + t + 4]);
            }
            #pragma unroll
            for (int nt = 0; nt < 4; nt++) {
                int c = wCol + nt * 8 + g;
                bf[nt][0] = __float_as_uint(Bs[s][c][k0 + t]);
                bf[nt][1] = __float_as_uint(Bs[s][c][k0 + t + 4]);
            }
            #pragma unroll
            for (int mt = 0; mt < 4; mt++)
                #pragma unroll
                for (int nt = 0; nt < 4; nt++) {
                    asm volatile(
                        "mma.sync.aligned.m16n8k8.row.col.f32.tf32.tf32.f32 "
                        "{%0,%1,%2,%3}, {%4,%5,%6,%7}, {%8,%9}, {%0,%1,%2,%3};"
                        : "+f"(acc[mt][nt][0]), "+f"(acc[mt][nt][1]),
                          "+f"(acc[mt][nt][2]), "+f"(acc[mt][nt][3])
                        : "r"(af[mt][0]), "r"(af[mt][1]), "r"(af[mt][2]), "r"(af[mt][3]),
                          "r"(bf[nt][0]), "r"(bf[nt][1]));
                }
        }
        __syncthreads();
        if (kt + 2 < KT) load_stage(s, kt + 2);
        CP_COMMIT();
        CP_WAIT1();
        __syncthreads();
    }

    #pragma unroll
    for (int mt = 0; mt < 4; mt++) {
        int r0 = bRow + wRow + mt * 16 + g;
        #pragma unroll
        for (int nt = 0; nt < 4; nt++) {
            int c0 = bCol + wCol + nt * 8 + t * 2;
            float bv0 = bias[c0], bv1 = bias[c0 + 1];
            float v0 = acc[mt][nt][0] + bv0;
            float v1 = acc[mt][nt][1] + bv1;
            float v2 = acc[mt][nt][2] + bv0;
            float v3 = acc[mt][nt][3] + bv1;
            if (ACT == ACT_RELU) {
                v0 = fmaxf(v0, 0.f); v1 = fmaxf(v1, 0.f);
                v2 = fmaxf(v2, 0.f); v3 = fmaxf(v3, 0.f);
            } else if (ACT == ACT_TANH) {
                v0 = tanh_hw(v0); v1 = tanh_hw(v1);
                v2 = tanh_hw(v2); v3 = tanh_hw(v3);
            }
            if (ROUND) {
                v0 = tf32_rna(v0); v1 = tf32_rna(v1);
                v2 = tf32_rna(v2); v3 = tf32_rna(v3);
            }
            float2 p0; p0.x = v0; p0.y = v1;
            float2 p1; p1.x = v2; p1.y = v3;
            *(float2*)(C + (size_t)r0 * N + c0)       = p0;
            *(float2*)(C + (size_t)(r0 + 8) * N + c0) = p1;
        }
    }
#else
    (void)A; (void)B; (void)bias; (void)C; (void)M; (void)N; (void)K;
#endif
}

// ---------------- launch ----------------
extern "C" void kernel_launch(void* const* d_in, const int* in_sizes, int n_in,
                              void* d_out, int out_size) {
    (void)in_sizes; (void)n_in; (void)out_size;
    const float* x  = (const float*)d_in[0];
    const float* Wg = (const float*)d_in[1];
    const float* We = (const float*)d_in[2];
    const float* be = (const float*)d_in[3];
    const float* W1 = (const float*)d_in[4];
    const float* b1 = (const float*)d_in[5];
    const float* W2 = (const float*)d_in[6];
    const float* b2 = (const float*)d_in[7];
    const float* Wo = (const float*)d_in[8];
    const float* bo = (const float*)d_in[9];
    float* out = (float*)d_out;

    float *A0, *actA, *actB, *Wef, *W1c, *W2c, *Woc, *beS;
    cudaGetSymbolAddress((void**)&A0,  g_A0);
    cudaGetSymbolAddress((void**)&actA, g_actA);
    cudaGetSymbolAddress((void**)&actB, g_actB);
    cudaGetSymbolAddress((void**)&Wef, g_Wef);
    cudaGetSymbolAddress((void**)&W1c, g_W1c);
    cudaGetSymbolAddress((void**)&W2c, g_W2c);
    cudaGetSymbolAddress((void**)&Woc, g_Woc);
    cudaGetSymbolAddress((void**)&beS, g_beS);

    cudaFuncSetAttribute(gemm_tc<ACT_RELU, true>,
                         cudaFuncAttributeMaxDynamicSharedMemorySize, GEMM_SMEM_BYTES);
    cudaFuncSetAttribute(gemm_tc<ACT_TANH, true>,
                         cudaFuncAttributeMaxDynamicSharedMemorySize, GEMM_SMEM_BYTES);
    cudaFuncSetAttribute(gemm_tc<ACT_NONE, false>,
                         cudaFuncAttributeMaxDynamicSharedMemorySize, GEMM_SMEM_BYTES);

    // weight prep (cheap, idempotent)
    prep_we<<<(ESZ * DIN + 255) / 256, 256>>>(We, Wef);
    prep_cvt<<<(H1SZ * ESZ + 255) / 256, 256>>>(W1, W1c, H1SZ * ESZ);
    prep_cvt<<<(H2SZ * H1SZ + 255) / 256, 256>>>(W2, W2c, H2SZ * H1SZ);
    prep_cvt<<<(OSZ * H2SZ + 255) / 256, 256>>>(Wo, Woc, OSZ * H2SZ);
    prep_besum<<<(ESZ + 255) / 256, 256>>>(be, beS);

    // gates + gated/rounded A0
    gate_kernel<<<NROWS / 8, 256>>>(x, Wg, A0);

    // Fallback chain (no-op bodies when the sm_103a-specific cubin is loaded)
    gemm_fb<ACT_RELU, true><<<dim3(ESZ / 128, NROWS / 128), 256>>>(A0, Wef, beS, actA, NROWS, ESZ, DIN);
    gemm_fb<ACT_TANH, true><<<dim3(H1SZ / 128, NROWS / 128), 256>>>(actA, W1c, b1, actB, NROWS, H1SZ, ESZ);
    gemm_fb<ACT_TANH, true><<<dim3(H2SZ / 128, NROWS / 128), 256>>>(actB, W2c, b2, actA, NROWS, H2SZ, H1SZ);
    gemm_fb<ACT_NONE, false><<<dim3(OSZ / 128, NROWS / 128), 256>>>(actA, Woc, bo, out, NROWS, OSZ, H2SZ);

    // tcgen05 chain (no-op bodies in the generic pass): BM=256, BN=256
    gemm_tc<ACT_RELU, true><<<dim3(ESZ / 256, NROWS / 256), 128, GEMM_SMEM_BYTES>>>(
        A0, Wef, beS, actA, ESZ, DIN);
    gemm_tc<ACT_TANH, true><<<dim3(H1SZ / 256, NROWS / 256), 128, GEMM_SMEM_BYTES>>>(
        actA, W1c, b1, actB, H1SZ, ESZ);
    gemm_tc<ACT_TANH, true><<<dim3(H2SZ / 256, NROWS / 256), 128, GEMM_SMEM_BYTES>>>(
        actB, W2c, b2, actA, H2SZ, H1SZ);
    gemm_tc<ACT_NONE, false><<<dim3(OSZ / 256, NROWS / 256), 128, GEMM_SMEM_BYTES>>>(
        actA, Woc, bo, out, OSZ, H2SZ);
}